// round 17
// baseline (speedup 1.0000x reference)
#include <cuda_runtime.h>
#include <cuda_fp16.h>
#include <cstdint>

#define NN  100000
#define EP  1600000
#define ET  3200000
#define FIN 128
#define FH  64
#define FO  32
#define NB  ((NN + 255) / 256)   // 391 scan blocks

// ---------------- scratch (static device globals; no allocation) ------------
__device__ int    g_deg[NN];               // self-cleaning: scanC re-zeros
__device__ int    g_bsum[512];
__device__ int    g_rowptr[NN + 1];
__device__ int    g_cursor[NN];
__device__ uint2  g_edge[EP];              // {src, __float_as_uint(dinv[src])}
__device__ float  g_dinv[NN];
__device__ __half g_xw[(size_t)NN * FH];   // layer1 linear out (fp16 storage)
__device__ __half g_hw[(size_t)NN * FO];   // layer2 linear out (fp16 storage)
__device__ __half g_z [(size_t)NN * FO];   // layer2 embedding (fp16 storage)

__device__ __forceinline__ int edge_at(const void* p, int is64, size_t idx) {
    if (is64) return (int)((const long long*)p)[idx];
    return ((const int*)p)[idx];
}

// unpack uint4 (8 halves) -> 8 floats
struct F8 { float f[8]; };
__device__ __forceinline__ F8 h8_to_f8(uint4 u) {
    F8 r;
    float2 a = __half22float2(*(__half2*)&u.x);
    float2 b = __half22float2(*(__half2*)&u.y);
    float2 c = __half22float2(*(__half2*)&u.z);
    float2 d = __half22float2(*(__half2*)&u.w);
    r.f[0] = a.x; r.f[1] = a.y; r.f[2] = b.x; r.f[3] = b.y;
    r.f[4] = c.x; r.f[5] = c.y; r.f[6] = d.x; r.f[7] = d.y;
    return r;
}

// per-warp dtype probe: odd 32-bit words are int64 high words (all 0) for i64,
// ~random node ids for i32. Call with ALL lanes active (kernel entry).
__device__ __forceinline__ int probe_is64(const int* p) {
    int lane = threadIdx.x & 31;
    unsigned m = __ballot_sync(0xffffffffu, p[2 * lane + 1] != 0);
    return m == 0;
}

// ---------------- degree histogram (2 edges / thread) ------------------------
__global__ void k_hist(const void* __restrict__ eidx) {
    int is64 = probe_is64((const int*)eidx);
    int i = blockIdx.x * blockDim.x + threadIdx.x;
    if (i * 2 >= EP) return;
    int c0, c1;
    if (is64) {
        longlong2 v = ((const longlong2*)((const long long*)eidx + EP))[i];
        c0 = (int)v.x; c1 = (int)v.y;
    } else {
        int2 v = ((const int2*)((const int*)eidx + EP))[i];
        c0 = v.x; c1 = v.y;
    }
    atomicAdd(&g_deg[c0], 1);
    atomicAdd(&g_deg[c1], 1);
}

// ---------------- scan phase A: per-block sums -------------------------------
__global__ __launch_bounds__(256) void k_scanA() {
    int i = blockIdx.x * 256 + threadIdx.x;
    int lane = threadIdx.x & 31, wid = threadIdx.x >> 5;
    __shared__ int sw[8];
    int v = (i < NN) ? g_deg[i] : 0;
    #pragma unroll
    for (int o = 16; o; o >>= 1) v += __shfl_xor_sync(0xffffffffu, v, o);
    if (lane == 0) sw[wid] = v;
    __syncthreads();
    if (threadIdx.x == 0) {
        int t = 0;
        #pragma unroll
        for (int j = 0; j < 8; j++) t += sw[j];
        g_bsum[blockIdx.x] = t;
    }
}

// ---------------- scan phase C (B fused): offsets + dinv + deg self-clean ----
__global__ __launch_bounds__(256) void k_scanC() {
    __shared__ int sred[8];
    __shared__ int sw[8];
    __shared__ int s_total;
    int tid = threadIdx.x, lane = tid & 31, wid = tid >> 5;
    int part = 0;
    for (int t = tid; t < blockIdx.x; t += 256) part += g_bsum[t];
    #pragma unroll
    for (int o = 16; o; o >>= 1) part += __shfl_xor_sync(0xffffffffu, part, o);
    if (lane == 0) sred[wid] = part;
    __syncthreads();
    int off = sred[0] + sred[1] + sred[2] + sred[3]
            + sred[4] + sred[5] + sred[6] + sred[7];
    int i = blockIdx.x * 256 + tid;
    int v = (i < NN) ? g_deg[i] : 0;
    int incl = v;
    #pragma unroll
    for (int o = 1; o < 32; o <<= 1) {
        int n = __shfl_up_sync(0xffffffffu, incl, o);
        if (lane >= o) incl += n;
    }
    if (lane == 31) sw[wid] = incl;
    __syncthreads();
    if (tid == 0) {
        int run = 0;
        #pragma unroll
        for (int j = 0; j < 8; j++) { int x = sw[j]; sw[j] = run; run += x; }
        s_total = run;
    }
    __syncthreads();
    int excl = off + sw[wid] + incl - v;
    if (i < NN) {
        g_rowptr[i] = excl;
        g_cursor[i] = excl;
        g_dinv[i]   = rsqrtf((float)(v + 1));
        g_deg[i]    = 0;
    }
    if (blockIdx.x == NB - 1 && tid == 0) g_rowptr[NN] = off + s_total;
}

// ---------------- CSR scatter: pack {src, dinv[src]} ------------------------
__global__ void k_scatter(const void* __restrict__ eidx) {
    int is64 = probe_is64((const int*)eidx);
    int i = blockIdx.x * blockDim.x + threadIdx.x;
    if (i * 2 >= EP) return;
    int r0, r1, c0, c1;
    if (is64) {
        const long long* e64 = (const long long*)eidx;
        longlong2 vr = ((const longlong2*)e64)[i];
        longlong2 vc = ((const longlong2*)(e64 + EP))[i];
        r0 = (int)vr.x; r1 = (int)vr.y;
        c0 = (int)vc.x; c1 = (int)vc.y;
    } else {
        const int* e32 = (const int*)eidx;
        int2 vr = ((const int2*)e32)[i];
        int2 vc = ((const int2*)(e32 + EP))[i];
        r0 = vr.x; r1 = vr.y;
        c0 = vc.x; c1 = vc.y;
    }
    float d0 = g_dinv[r0], d1 = g_dinv[r1];
    int p0 = atomicAdd(&g_cursor[c0], 1);
    g_edge[p0] = make_uint2((unsigned)r0, __float_as_uint(d0));
    int p1 = atomicAdd(&g_cursor[c1], 1);
    g_edge[p1] = make_uint2((unsigned)r1, __float_as_uint(d1));
}

// ---------------- GEMM1: 8 rows x 8 cols per thread, fp16 output -------------
__global__ __launch_bounds__(256) void k_gemm1(const float* __restrict__ x,
                                               const float* __restrict__ W) {
    __shared__ float Ws[FIN * FH];                // 32 KB
    int tx = threadIdx.x, ty = threadIdx.y;       // (8, 32)
    int tid = ty * 8 + tx;
    {
        const float4* W4 = (const float4*)W;
        float4* Ws4 = (float4*)Ws;
        for (int i = tid; i < FIN * FH / 4; i += 256) Ws4[i] = W4[i];
    }
    __syncthreads();
    int rbase = blockIdx.x * 256 + ty;            // rows: rbase + 32*i, i<8
    int cb = tx * 8;
    const float4* xp[8];
    bool vr[8];
    #pragma unroll
    for (int i = 0; i < 8; i++) {
        int r = rbase + i * 32;
        vr[i] = r < NN;
        xp[i] = (const float4*)(x + (size_t)(vr[i] ? r : 0) * FIN);
    }
    float acc[8][8];
    #pragma unroll
    for (int i = 0; i < 8; i++)
        #pragma unroll
        for (int j = 0; j < 8; j++) acc[i][j] = 0.f;
    for (int k4 = 0; k4 < FIN / 4; k4++) {
        float4 xv[8];
        #pragma unroll
        for (int i = 0; i < 8; i++) xv[i] = xp[i][k4];
        const float* w = &Ws[(k4 * 4) * FH + cb];
        #pragma unroll
        for (int kk = 0; kk < 4; kk++) {
            const float* wk = w + kk * FH;
            #pragma unroll
            for (int j = 0; j < 8; j++) {
                float wv = wk[j];
                #pragma unroll
                for (int i = 0; i < 8; i++)
                    acc[i][j] = fmaf(((const float*)&xv[i])[kk], wv, acc[i][j]);
            }
        }
    }
    #pragma unroll
    for (int i = 0; i < 8; i++) {
        if (vr[i]) {
            uint4 st;
            __half2 p0 = __floats2half2_rn(acc[i][0], acc[i][1]);
            __half2 p1 = __floats2half2_rn(acc[i][2], acc[i][3]);
            __half2 p2 = __floats2half2_rn(acc[i][4], acc[i][5]);
            __half2 p3 = __floats2half2_rn(acc[i][6], acc[i][7]);
            st.x = *(unsigned*)&p0; st.y = *(unsigned*)&p1;
            st.z = *(unsigned*)&p2; st.w = *(unsigned*)&p3;
            *(uint4*)(g_xw + (size_t)(rbase + i * 32) * FH + cb) = st;
        }
    }
}

// ---------------- agg1 fused with GEMM2: uint4 rows, 4 groups x 8 lanes ------
__global__ __launch_bounds__(256) void k_agg1f(const float* __restrict__ b1,
                                               const float* __restrict__ W2) {
    __shared__ float Ws[FH * FO];                 // 8 KB
    int tid = threadIdx.x;
    {
        const float4* W4 = (const float4*)W2;
        float4* Ws4 = (float4*)Ws;
        for (int i = tid; i < FH * FO / 4; i += 256) Ws4[i] = W4[i];
    }
    __syncthreads();
    int w = (blockIdx.x * 256 + tid) >> 5;
    if (w >= NN) return;
    int lane = tid & 31;
    int grp = lane >> 3, q = lane & 7;            // q: 16B chunk of 128B row
    float dw = g_dinv[w];
    float a[8];
    #pragma unroll
    for (int j = 0; j < 8; j++) a[j] = 0.f;
    if (grp == 0) {                               // self loop on group 0
        F8 sv = h8_to_f8(((const uint4*)(g_xw + (size_t)w * FH))[q]);
        #pragma unroll
        for (int j = 0; j < 8; j++) a[j] = sv.f[j] * dw;
    }
    int s = g_rowptr[w], e = g_rowptr[w + 1];
    int p = s;
    for (; p + 16 <= e; p += 16) {                // 4 slots x 4 groups
        uint2 r[4];
        #pragma unroll
        for (int t = 0; t < 4; t++) r[t] = g_edge[p + 4 * t + grp];
        uint4 u[4];
        #pragma unroll
        for (int t = 0; t < 4; t++)
            u[t] = ((const uint4*)(g_xw + (size_t)r[t].x * FH))[q];
        #pragma unroll
        for (int t = 0; t < 4; t++) {
            float d = __uint_as_float(r[t].y);
            F8 f = h8_to_f8(u[t]);
            #pragma unroll
            for (int j = 0; j < 8; j++) a[j] = fmaf(f.f[j], d, a[j]);
        }
    }
    for (; p + 8 <= e; p += 8) {                  // 2 slots
        uint2 r0 = g_edge[p + grp];
        uint2 r1 = g_edge[p + 4 + grp];
        uint4 u0 = ((const uint4*)(g_xw + (size_t)r0.x * FH))[q];
        uint4 u1 = ((const uint4*)(g_xw + (size_t)r1.x * FH))[q];
        float d0 = __uint_as_float(r0.y), d1 = __uint_as_float(r1.y);
        F8 f0 = h8_to_f8(u0), f1 = h8_to_f8(u1);
        #pragma unroll
        for (int j = 0; j < 8; j++) a[j] = fmaf(f0.f[j], d0, a[j]);
        #pragma unroll
        for (int j = 0; j < 8; j++) a[j] = fmaf(f1.f[j], d1, a[j]);
    }
    for (; p + 4 <= e; p += 4) {                  // 1 slot
        uint2 r0 = g_edge[p + grp];
        uint4 u0 = ((const uint4*)(g_xw + (size_t)r0.x * FH))[q];
        float d0 = __uint_as_float(r0.y);
        F8 f0 = h8_to_f8(u0);
        #pragma unroll
        for (int j = 0; j < 8; j++) a[j] = fmaf(f0.f[j], d0, a[j]);
    }
    if (p < e) {                                  // 1..3 edges: group predicate
        int rem = e - p;
        uint2 r0 = g_edge[p + (grp < rem ? grp : 0)];
        uint4 u0 = ((const uint4*)(g_xw + (size_t)r0.x * FH))[q];
        float d0 = (grp < rem) ? __uint_as_float(r0.y) : 0.f;
        F8 f0 = h8_to_f8(u0);
        #pragma unroll
        for (int j = 0; j < 8; j++) a[j] = fmaf(f0.f[j], d0, a[j]);
    }
    // combine 4 groups
    #pragma unroll
    for (int o = 8; o <= 16; o <<= 1) {
        #pragma unroll
        for (int j = 0; j < 8; j++)
            a[j] += __shfl_xor_sync(0xffffffffu, a[j], o);
    }
    // bias + relu: lane q holds features 8q..8q+7
    float4 bj0 = ((const float4*)b1)[2 * q];
    float4 bj1 = ((const float4*)b1)[2 * q + 1];
    float h[8];
    h[0] = fmaxf(fmaf(a[0], dw, bj0.x), 0.f);
    h[1] = fmaxf(fmaf(a[1], dw, bj0.y), 0.f);
    h[2] = fmaxf(fmaf(a[2], dw, bj0.z), 0.f);
    h[3] = fmaxf(fmaf(a[3], dw, bj0.w), 0.f);
    h[4] = fmaxf(fmaf(a[4], dw, bj1.x), 0.f);
    h[5] = fmaxf(fmaf(a[5], dw, bj1.y), 0.f);
    h[6] = fmaxf(fmaf(a[6], dw, bj1.z), 0.f);
    h[7] = fmaxf(fmaf(a[7], dw, bj1.w), 0.f);
    // GEMM2 epilogue: hw[lane] = sum_k h[k]*W2[k][lane]; h[k] at lane k>>3
    float o = 0.f;
    #pragma unroll
    for (int k8 = 0; k8 < 8; k8++) {
        #pragma unroll
        for (int j = 0; j < 8; j++) {
            float hk = __shfl_sync(0xffffffffu, h[j], k8);
            o = fmaf(hk, Ws[(k8 * 8 + j) * FO + lane], o);
        }
    }
    g_hw[(size_t)w * FO + lane] = __float2half_rn(o);
}

// ---------------- agg2: uint4 rows, 8 groups x 4 lanes; z fp16 ---------------
__global__ __launch_bounds__(256) void k_agg2(const float* __restrict__ b) {
    int w = (blockIdx.x * 256 + threadIdx.x) >> 5;
    if (w >= NN) return;
    int lane = threadIdx.x & 31;
    int grp = lane >> 2, l4 = lane & 3;           // l4: 16B chunk of 64B row
    float dw = g_dinv[w];
    float a[8];
    #pragma unroll
    for (int j = 0; j < 8; j++) a[j] = 0.f;
    if (grp == 0) {
        F8 sv = h8_to_f8(((const uint4*)(g_hw + (size_t)w * FO))[l4]);
        #pragma unroll
        for (int j = 0; j < 8; j++) a[j] = sv.f[j] * dw;
    }
    int s = g_rowptr[w], e = g_rowptr[w + 1];
    int p = s;
    for (; p + 16 <= e; p += 16) {                // 2 slots x 8 groups
        uint2 r0 = g_edge[p     + grp];
        uint2 r1 = g_edge[p + 8 + grp];
        uint4 u0 = ((const uint4*)(g_hw + (size_t)r0.x * FO))[l4];
        uint4 u1 = ((const uint4*)(g_hw + (size_t)r1.x * FO))[l4];
        float d0 = __uint_as_float(r0.y), d1 = __uint_as_float(r1.y);
        F8 f0 = h8_to_f8(u0), f1 = h8_to_f8(u1);
        #pragma unroll
        for (int j = 0; j < 8; j++) a[j] = fmaf(f0.f[j], d0, a[j]);
        #pragma unroll
        for (int j = 0; j < 8; j++) a[j] = fmaf(f1.f[j], d1, a[j]);
    }
    for (; p + 8 <= e; p += 8) {                  // 1 slot
        uint2 r0 = g_edge[p + grp];
        uint4 u0 = ((const uint4*)(g_hw + (size_t)r0.x * FO))[l4];
        float d0 = __uint_as_float(r0.y);
        F8 f0 = h8_to_f8(u0);
        #pragma unroll
        for (int j = 0; j < 8; j++) a[j] = fmaf(f0.f[j], d0, a[j]);
    }
    if (p < e) {                                  // 1..7 edges: group predicate
        int rem = e - p;
        uint2 r0 = g_edge[p + (grp < rem ? grp : 0)];
        uint4 u0 = ((const uint4*)(g_hw + (size_t)r0.x * FO))[l4];
        float d0 = (grp < rem) ? __uint_as_float(r0.y) : 0.f;
        F8 f0 = h8_to_f8(u0);
        #pragma unroll
        for (int j = 0; j < 8; j++) a[j] = fmaf(f0.f[j], d0, a[j]);
    }
    // combine 8 groups
    #pragma unroll
    for (int o = 4; o <= 16; o <<= 1) {
        #pragma unroll
        for (int j = 0; j < 8; j++)
            a[j] += __shfl_xor_sync(0xffffffffu, a[j], o);
    }
    if (grp == 0) {
        float4 bj0 = ((const float4*)b)[2 * l4];
        float4 bj1 = ((const float4*)b)[2 * l4 + 1];
        __half2 z0 = __floats2half2_rn(fmaf(a[0], dw, bj0.x),
                                       fmaf(a[1], dw, bj0.y));
        __half2 z1 = __floats2half2_rn(fmaf(a[2], dw, bj0.z),
                                       fmaf(a[3], dw, bj0.w));
        __half2 z2 = __floats2half2_rn(fmaf(a[4], dw, bj1.x),
                                       fmaf(a[5], dw, bj1.y));
        __half2 z3 = __floats2half2_rn(fmaf(a[6], dw, bj1.z),
                                       fmaf(a[7], dw, bj1.w));
        uint4 st;
        st.x = *(unsigned*)&z0; st.y = *(unsigned*)&z1;
        st.z = *(unsigned*)&z2; st.w = *(unsigned*)&z3;
        ((uint4*)(g_z + (size_t)w * FO))[l4] = st;   // 16B/lane, 64B row
    }
}

// ---------------- decode: 32 edges/warp, 4 per 4-lane subgroup, uint4 --------
__global__ __launch_bounds__(256) void k_decode(const void* __restrict__ pos,
                                                const void* __restrict__ neg,
                                                float* __restrict__ out) {
    int is64 = probe_is64((const int*)pos);
    int warp = (blockIdx.x * 256 + threadIdx.x) >> 5;
    int lane = threadIdx.x & 31;
    int sub = lane >> 2, l4 = lane & 3;
    size_t base = (size_t)warp * 32 + sub * 4;      // EP%4==0: one-sided
    const void* buf; size_t off;
    if (base < EP) { buf = pos; off = base; }
    else           { buf = neg; off = base - EP; }
    int a[4], c[4];
    if (!is64) {
        const int* e32 = (const int*)buf;
        int4 a0 = *(const int4*)(e32 + off);
        int4 c0 = *(const int4*)(e32 + EP + off);
        a[0] = a0.x; a[1] = a0.y; a[2] = a0.z; a[3] = a0.w;
        c[0] = c0.x; c[1] = c0.y; c[2] = c0.z; c[3] = c0.w;
    } else {
        const long long* e64 = (const long long*)buf;
        #pragma unroll
        for (int t = 0; t < 2; t++) {
            longlong2 pa = *(const longlong2*)(e64 + off + 2 * t);
            longlong2 pc = *(const longlong2*)(e64 + EP + off + 2 * t);
            a[2 * t] = (int)pa.x; a[2 * t + 1] = (int)pa.y;
            c[2 * t] = (int)pc.x; c[2 * t + 1] = (int)pc.y;
        }
    }
    uint4 ua[4], ub[4];
    #pragma unroll
    for (int t = 0; t < 4; t++) {
        ua[t] = ((const uint4*)(g_z + (size_t)a[t] * FO))[l4];
        ub[t] = ((const uint4*)(g_z + (size_t)c[t] * FO))[l4];
    }
    float v[4];
    #pragma unroll
    for (int t = 0; t < 4; t++) {
        F8 fa = h8_to_f8(ua[t]);
        F8 fb = h8_to_f8(ub[t]);
        float sum = 0.f;
        #pragma unroll
        for (int j = 0; j < 8; j++) sum = fmaf(fa.f[j], fb.f[j], sum);
        v[t] = sum;
    }
    #pragma unroll
    for (int o = 2; o; o >>= 1) {
        #pragma unroll
        for (int t = 0; t < 4; t++) v[t] += __shfl_xor_sync(0xffffffffu, v[t], o);
    }
    if (l4 == 0)
        ((float4*)out)[base >> 2] = make_float4(v[0], v[1], v[2], v[3]);
}

// edge_index echoed as floats (2 elems / thread) ------------------------------
__global__ void k_tail(const void* __restrict__ pos,
                       const void* __restrict__ neg,
                       float* __restrict__ out, int count) {
    int is64 = probe_is64((const int*)pos);
    int i = (blockIdx.x * blockDim.x + threadIdx.x) * 2;
    if (i >= count) return;
    int r = i / ET, c = i % ET;                    // ET%2==0: pair same row
    int v0, v1;
    const void* buf = (c < EP) ? pos : neg;
    size_t off = (size_t)r * EP + ((c < EP) ? c : c - EP);
    if (c + 1 == EP || c + 1 == ET) {              // straddle: scalar
        v0 = edge_at(buf, is64, off);
        v1 = (c + 1 < ET) ? edge_at(neg, is64, (size_t)r * EP) :
             ((r == 0) ? edge_at(pos, is64, EP) : 0);
        out[ET + i] = (float)v0;
        if (i + 1 < count) out[ET + i + 1] = (float)v1;
        return;
    }
    if (is64) {
        longlong2 p2 = ((const longlong2*)((const long long*)buf))[off / 2];
        v0 = (int)p2.x; v1 = (int)p2.y;
    } else {
        int2 p2 = ((const int2*)((const int*)buf))[off / 2];
        v0 = p2.x; v1 = p2.y;
    }
    ((float2*)(out + ET))[i / 2] = make_float2((float)v0, (float)v1);
}

// ---------------- launcher ---------------------------------------------------
extern "C" void kernel_launch(void* const* d_in, const int* in_sizes, int n_in,
                              void* d_out, int out_size) {
    static cudaStream_t s2 = 0;
    static cudaEvent_t evFork = 0, evJoin = 0, evTail = 0;
    if (!s2) {
        cudaStreamCreateWithFlags(&s2, cudaStreamNonBlocking);
        cudaEventCreateWithFlags(&evFork, cudaEventDisableTiming);
        cudaEventCreateWithFlags(&evJoin, cudaEventDisableTiming);
        cudaEventCreateWithFlags(&evTail, cudaEventDisableTiming);
    }

    const float *x = 0, *W1 = 0, *b1 = 0, *W2 = 0, *b2 = 0;
    const void *pos = 0, *neg = 0;
    for (int i = 0; i < n_in; i++) {
        switch (in_sizes[i]) {
            case NN * FIN:  x  = (const float*)d_in[i]; break;
            case FIN * FH:  W1 = (const float*)d_in[i]; break;
            case FH:        b1 = (const float*)d_in[i]; break;
            case FH * FO:   W2 = (const float*)d_in[i]; break;
            case FO:        b2 = (const float*)d_in[i]; break;
            case 2 * EP:
                if (!pos) pos = d_in[i];
                else      neg = d_in[i];
                break;
            default: break;
        }
    }
    float* out = (float*)d_out;

    // fork: GEMM1 + edge echo (independent of graph preprocessing) on s2
    cudaEventRecord(evFork, 0);
    cudaStreamWaitEvent(s2, evFork, 0);
    k_gemm1<<<(NN + 255) / 256, dim3(8, 32), 0, s2>>>(x, W1);
    cudaEventRecord(evJoin, s2);
    int cnt = 0;
    if (out_size > ET) {
        cnt = out_size - ET;
        if (cnt > 2 * ET) cnt = 2 * ET;
        k_tail<<<((cnt + 1) / 2 + 255) / 256, 256, 0, s2>>>(pos, neg, out, cnt);
        cudaEventRecord(evTail, s2);
    }

    // preprocessing chain on main stream (deg pre-zeroed: self-cleaning)
    k_hist   <<<(EP / 2 + 255) / 256, 256>>>(pos);
    k_scanA  <<<NB, 256>>>();
    k_scanC  <<<NB, 256>>>();
    k_scatter<<<(EP / 2 + 255) / 256, 256>>>(pos);

    // join gemm1, then fused layer pipeline (flat grids)
    cudaStreamWaitEvent(0, evJoin, 0);
    k_agg1f<<<(NN * 32 + 255) / 256, 256>>>(b1, W2);
    k_agg2 <<<(NN * 32 + 255) / 256, 256>>>(b2);

    // decode writes out[0..ET), tail writes out[ET..): disjoint — join after
    k_decode<<<(ET / 32) * 32 / 256, 256>>>(pos, neg, out);
    if (cnt) cudaStreamWaitEvent(0, evTail, 0);
}